// round 9
// baseline (speedup 1.0000x reference)
#include <cuda_runtime.h>
#include <cuda_bf16.h>

#define N_NODES_MAX 50000
#define N_EDGES_MAX 800000
#define D 64
#define SCAN_B 1024
#define MAX_SBLK ((N_NODES_MAX + SCAN_B - 1) / SCAN_B)   // 49
#define BLK 1024
#define WPB (BLK / 32)   // warps (=nodes) per block

// Scratch (no cudaMalloc allowed)
__device__ float g_h1  [N_NODES_MAX * D];
__device__ int   g_deg [N_NODES_MAX];
__device__ int   g_off [N_NODES_MAX + 1];
__device__ int   g_cur [N_NODES_MAX];
__device__ int   g_eidx[N_EDGES_MAX];
__device__ int   g_bsum[MAX_SBLK + 1];

// ---------------------------------------------------------------------------
// CSR step 1: histogram of dst
// ---------------------------------------------------------------------------
__global__ void hist_kernel(const int* __restrict__ dst, int* __restrict__ deg,
                            int n_edges) {
    int i = blockIdx.x * blockDim.x + threadIdx.x;
    if (i < n_edges) atomicAdd(deg + __ldg(dst + i), 1);
}

// ---------------------------------------------------------------------------
// CSR step 2a: per-block sums of deg (coalesced)
// ---------------------------------------------------------------------------
__global__ __launch_bounds__(SCAN_B) void scanA_kernel(
    const int* __restrict__ deg, int* __restrict__ bsum, int n) {
    __shared__ int s[SCAN_B];
    int tid = threadIdx.x;
    int i = blockIdx.x * SCAN_B + tid;
    s[tid] = (i < n) ? deg[i] : 0;
    __syncthreads();
    #pragma unroll
    for (int o = SCAN_B / 2; o > 0; o >>= 1) {
        if (tid < o) s[tid] += s[tid + o];
        __syncthreads();
    }
    if (tid == 0) bsum[blockIdx.x] = s[0];
}

// ---------------------------------------------------------------------------
// CSR step 2b: exclusive scan of block sums (tiny, one block)
// ---------------------------------------------------------------------------
__global__ __launch_bounds__(64) void scanB_kernel(int* __restrict__ bsum, int nb) {
    __shared__ int s[64];
    int tid = threadIdx.x;
    int v = (tid < nb) ? bsum[tid] : 0;
    s[tid] = v;
    __syncthreads();
    #pragma unroll
    for (int o = 1; o < 64; o <<= 1) {
        int t = (tid >= o) ? s[tid - o] : 0;
        __syncthreads();
        s[tid] += t;
        __syncthreads();
    }
    if (tid < nb) bsum[tid] = s[tid] - v;
}

// ---------------------------------------------------------------------------
// CSR step 2c: per-element offsets
// ---------------------------------------------------------------------------
__global__ __launch_bounds__(SCAN_B) void scanC_kernel(
    const int* __restrict__ deg, const int* __restrict__ bsum,
    int* __restrict__ off, int* __restrict__ cur, int n) {
    __shared__ int s[SCAN_B];
    int tid = threadIdx.x;
    int i = blockIdx.x * SCAN_B + tid;
    int v = (i < n) ? deg[i] : 0;
    s[tid] = v;
    __syncthreads();
    #pragma unroll
    for (int o = 1; o < SCAN_B; o <<= 1) {
        int t = (tid >= o) ? s[tid - o] : 0;
        __syncthreads();
        s[tid] += t;
        __syncthreads();
    }
    int ex = bsum[blockIdx.x] + s[tid] - v;
    if (i < n) { off[i] = ex; cur[i] = ex; }
    if (i == n - 1) off[n] = ex + v;
}

// ---------------------------------------------------------------------------
// CSR step 3: fill
// ---------------------------------------------------------------------------
__global__ void fill_kernel(const int* __restrict__ src,
                            const int* __restrict__ dst,
                            int* __restrict__ cur, int* __restrict__ eidx,
                            int n_edges) {
    int i = blockIdx.x * blockDim.x + threadIdx.x;
    if (i < n_edges) {
        int p = atomicAdd(cur + __ldg(dst + i), 1);
        eidx[p] = __ldg(src + i);
    }
}

// ---------------------------------------------------------------------------
// Warp-level gather of one node's aggregate row into smem (16B-aligned).
// Half-warp per edge (16 lanes x float4), predicated 4-deep.
// ---------------------------------------------------------------------------
__device__ __forceinline__ void warp_gather_row(
    const float* __restrict__ h, const int* __restrict__ eidx,
    int o, int e, int lane, float* __restrict__ rowS) {
    int half = lane >> 4;
    int hl   = lane & 15;
    int last = max(o, e - 1);
    float4 acc = make_float4(0.f, 0.f, 0.f, 0.f);
    for (int i = o + half; i < e; i += 8) {
        int j1 = i + 2, j2 = i + 4, j3 = i + 6;
        int s0 = __ldg(eidx + i);
        int s1 = __ldg(eidx + min(j1, last));
        int s2 = __ldg(eidx + min(j2, last));
        int s3 = __ldg(eidx + min(j3, last));
        float m1 = (j1 < e) ? 1.f : 0.f;
        float m2 = (j2 < e) ? 1.f : 0.f;
        float m3 = (j3 < e) ? 1.f : 0.f;
        float4 v0 = *reinterpret_cast<const float4*>(h + (size_t)s0 * D + hl * 4);
        float4 v1 = *reinterpret_cast<const float4*>(h + (size_t)s1 * D + hl * 4);
        float4 v2 = *reinterpret_cast<const float4*>(h + (size_t)s2 * D + hl * 4);
        float4 v3 = *reinterpret_cast<const float4*>(h + (size_t)s3 * D + hl * 4);
        acc.x += v0.x + m1 * v1.x + m2 * v2.x + m3 * v3.x;
        acc.y += v0.y + m1 * v1.y + m2 * v2.y + m3 * v3.y;
        acc.z += v0.z + m1 * v1.z + m2 * v2.z + m3 * v3.z;
        acc.w += v0.w + m1 * v1.w + m2 * v2.w + m3 * v3.w;
    }
    acc.x += __shfl_down_sync(0xffffffffu, acc.x, 16);
    acc.y += __shfl_down_sync(0xffffffffu, acc.y, 16);
    acc.z += __shfl_down_sync(0xffffffffu, acc.z, 16);
    acc.w += __shfl_down_sync(0xffffffffu, acc.w, 16);
    if (half == 0)
        *reinterpret_cast<float4*>(rowS + hl * 4) = acc;
}

// ---------------------------------------------------------------------------
// Warp GEMM: lane j computes y[2j], y[2j+1] = relu(row @ W + b) columns.
// row broadcast from smem; W row-major [64][64] in smem. Both 16B-aligned.
// ---------------------------------------------------------------------------
__device__ __forceinline__ void warp_row_gemm(
    const float* __restrict__ rowS, const float* __restrict__ Ws,
    const float* __restrict__ bs, int j, float& y0, float& y1) {
    y0 = bs[2 * j];
    y1 = bs[2 * j + 1];
    #pragma unroll 4
    for (int kc = 0; kc < 16; kc++) {
        float4 r = *reinterpret_cast<const float4*>(rowS + kc * 4);
        const float* wbase = Ws + (kc * 4) * D + 2 * j;
        float2 w0 = *reinterpret_cast<const float2*>(wbase);
        float2 w1 = *reinterpret_cast<const float2*>(wbase + D);
        float2 w2 = *reinterpret_cast<const float2*>(wbase + 2 * D);
        float2 w3 = *reinterpret_cast<const float2*>(wbase + 3 * D);
        y0 += r.x * w0.x + r.y * w1.x + r.z * w2.x + r.w * w3.x;
        y1 += r.x * w0.y + r.y * w1.y + r.z * w2.y + r.w * w3.y;
    }
    y0 = fmaxf(y0, 0.f);
    y1 = fmaxf(y1, 0.f);
}

// ---------------------------------------------------------------------------
// Layer 1 fused: h1[node] = relu(gather(v)[node] @ W1 + b1)
// ---------------------------------------------------------------------------
__global__ __launch_bounds__(BLK) void layer1_kernel(
    const float* __restrict__ v, const int* __restrict__ eidx,
    const int* __restrict__ off, const float* __restrict__ W,
    const float* __restrict__ b, float* __restrict__ h1, int n) {
    __shared__ __align__(16) float Ws[D * D];      // 16 KB
    __shared__ __align__(16) float bs[D];
    __shared__ __align__(16) float rows[WPB][D];   // 8 KB
    int tid  = threadIdx.x;
    int wid  = tid >> 5;
    int lane = tid & 31;

    reinterpret_cast<float4*>(Ws)[tid] = reinterpret_cast<const float4*>(W)[tid];
    if (tid < D) bs[tid] = b[tid];
    __syncthreads();

    int node = blockIdx.x * WPB + wid;
    if (node >= n) return;
    int o = __ldg(off + node);
    int e = __ldg(off + node + 1);

    warp_gather_row(v, eidx, o, e, lane, rows[wid]);
    __syncwarp();

    float y0, y1;
    warp_row_gemm(rows[wid], Ws, bs, lane, y0, y1);
    *reinterpret_cast<float2*>(h1 + (size_t)node * D + 2 * lane) =
        make_float2(y0, y1);
}

// ---------------------------------------------------------------------------
// Layer 2 fused: h2 = relu(gather(h1) @ W2 + b2); xa = h2@Wa+ba; xb = h2@Wb+bb
// Head matrices combined into Wh [64][18] (cols 0..15 = Wb, 16..17 = Wa).
// ---------------------------------------------------------------------------
__global__ __launch_bounds__(BLK) void layer2_kernel(
    const float* __restrict__ h1, const int* __restrict__ eidx,
    const int* __restrict__ off, const float* __restrict__ W,
    const float* __restrict__ b,
    const float* __restrict__ Wa, const float* __restrict__ ba,
    const float* __restrict__ Wb, const float* __restrict__ bb,
    float* __restrict__ xa_out, float* __restrict__ xb_out, int n) {
    __shared__ __align__(16) float Ws[D * D];        // 16 KB
    __shared__ __align__(16) float bs[D];
    __shared__ __align__(16) float Wh[D * 18];       // 4.5 KB combined heads
    __shared__ __align__(16) float bh[18];
    __shared__ __align__(16) float rows[WPB][D];     // 8 KB
    int tid  = threadIdx.x;
    int wid  = tid >> 5;
    int lane = tid & 31;

    reinterpret_cast<float4*>(Ws)[tid] = reinterpret_cast<const float4*>(W)[tid];
    if (tid < D) bs[tid] = b[tid];
    // combined head matrix: Wh[k][t] = (t<16) ? Wb[k][t] : Wa[k][t-16]
    for (int i = tid; i < D * 18; i += BLK) {
        int k = i / 18, t = i % 18;
        Wh[i] = (t < 16) ? Wb[k * 16 + t] : Wa[k * 2 + (t - 16)];
    }
    if (tid < 18) bh[tid] = (tid < 16) ? bb[tid] : ba[tid - 16];
    __syncthreads();

    int node = blockIdx.x * WPB + wid;
    if (node >= n) return;
    int o = __ldg(off + node);
    int e = __ldg(off + node + 1);

    warp_gather_row(h1, eidx, o, e, lane, rows[wid]);
    __syncwarp();

    float y0, y1;
    warp_row_gemm(rows[wid], Ws, bs, lane, y0, y1);
    __syncwarp();                      // all reads of rows[wid] done
    rows[wid][2 * lane]     = y0;      // overwrite with h2 row
    rows[wid][2 * lane + 1] = y1;
    __syncwarp();

    if (lane < 18) {
        float s = bh[lane];
        const float* r = rows[wid];
        #pragma unroll 8
        for (int k = 0; k < D; k++)
            s += r[k] * Wh[k * 18 + lane];
        if (lane < 16) xb_out[(size_t)node * 16 + lane] = s;
        else           xa_out[(size_t)node * 2 + (lane - 16)] = s;
    }
}

// ---------------------------------------------------------------------------
extern "C" void kernel_launch(void* const* d_in, const int* in_sizes, int n_in,
                              void* d_out, int out_size) {
    const float* v   = (const float*)d_in[0];
    const int*   src = (const int*)  d_in[1];
    const int*   dst = (const int*)  d_in[2];
    const float* W1  = (const float*)d_in[3];
    const float* b1  = (const float*)d_in[4];
    const float* W2  = (const float*)d_in[5];
    const float* b2  = (const float*)d_in[6];
    const float* Wa  = (const float*)d_in[7];
    const float* ba  = (const float*)d_in[8];
    const float* Wb  = (const float*)d_in[9];
    const float* bb  = (const float*)d_in[10];

    int n_nodes = in_sizes[0] / D;
    int n_edges = in_sizes[1];

    float* h1;   cudaGetSymbolAddress((void**)&h1,   g_h1);
    int*   deg;  cudaGetSymbolAddress((void**)&deg,  g_deg);
    int*   off;  cudaGetSymbolAddress((void**)&off,  g_off);
    int*   cur;  cudaGetSymbolAddress((void**)&cur,  g_cur);
    int*   eidx; cudaGetSymbolAddress((void**)&eidx, g_eidx);
    int*   bsum; cudaGetSymbolAddress((void**)&bsum, g_bsum);

    float* xa_out = (float*)d_out;
    float* xb_out = (float*)d_out + (size_t)n_nodes * 2;

    int edge_blocks  = (n_edges + 255) / 256;
    int scan_blocks  = (n_nodes + SCAN_B - 1) / SCAN_B;
    int layer_blocks = (n_nodes + WPB - 1) / WPB;

    // ---- CSR build (shared by both layers) ----
    cudaMemsetAsync(deg, 0, n_nodes * sizeof(int));
    hist_kernel <<<edge_blocks, 256>>>(dst, deg, n_edges);
    scanA_kernel<<<scan_blocks, SCAN_B>>>(deg, bsum, n_nodes);
    scanB_kernel<<<1, 64>>>(bsum, scan_blocks);
    scanC_kernel<<<scan_blocks, SCAN_B>>>(deg, bsum, off, cur, n_nodes);
    fill_kernel <<<edge_blocks, 256>>>(src, dst, cur, eidx, n_edges);

    // ---- Layer 1 fused (gather + GEMM + relu) ----
    layer1_kernel<<<layer_blocks, BLK>>>(v, eidx, off, W1, b1, h1, n_nodes);

    // ---- Layer 2 fused (gather + GEMM + relu + heads) ----
    layer2_kernel<<<layer_blocks, BLK>>>(h1, eidx, off, W2, b2,
                                         Wa, ba, Wb, bb,
                                         xa_out, xb_out, n_nodes);
}

// round 10
// speedup vs baseline: 1.1050x; 1.1050x over previous
#include <cuda_runtime.h>
#include <cuda_fp16.h>

#define N_NODES_MAX 50000
#define N_EDGES_MAX 800000
#define D 64
#define SCAN_B 1024
#define MAX_SBLK ((N_NODES_MAX + SCAN_B - 1) / SCAN_B)   // 49

// Scratch (no cudaMalloc allowed)
__device__ float  g_agg[N_NODES_MAX * D];
__device__ __align__(16) __half g_h1[N_NODES_MAX * D];   // layer-1 out, fp16
__device__ __align__(16) __half g_vh[N_NODES_MAX * D];   // v as fp16
__device__ int    g_deg [N_NODES_MAX];
__device__ int    g_off [N_NODES_MAX + 1];
__device__ int    g_cur [N_NODES_MAX];
__device__ int    g_eidx[N_EDGES_MAX];
__device__ int    g_bsum[MAX_SBLK + 1];

// ---------------------------------------------------------------------------
// Fused: v -> fp16 conversion (first conv_blocks) + dst histogram (rest)
// ---------------------------------------------------------------------------
__global__ void hist_conv_kernel(const int* __restrict__ dst,
                                 int* __restrict__ deg, int n_edges,
                                 const float4* __restrict__ v4,
                                 uint2* __restrict__ vh, int nconv,
                                 int conv_blocks) {
    int tid = threadIdx.x;
    if ((int)blockIdx.x < conv_blocks) {
        int j = blockIdx.x * 256 + tid;
        if (j < nconv) {
            float4 a = v4[j];
            uint2 o;
            __half2 p0 = __floats2half2_rn(a.x, a.y);
            __half2 p1 = __floats2half2_rn(a.z, a.w);
            o.x = *(unsigned*)&p0;
            o.y = *(unsigned*)&p1;
            vh[j] = o;
        }
    } else {
        int i = (blockIdx.x - conv_blocks) * 256 + tid;
        if (i < n_edges) atomicAdd(deg + __ldg(dst + i), 1);
    }
}

// ---------------------------------------------------------------------------
// CSR step 2a: per-block sums of deg (coalesced)
// ---------------------------------------------------------------------------
__global__ __launch_bounds__(SCAN_B) void scanA_kernel(
    const int* __restrict__ deg, int* __restrict__ bsum, int n) {
    __shared__ int s[SCAN_B];
    int tid = threadIdx.x;
    int i = blockIdx.x * SCAN_B + tid;
    s[tid] = (i < n) ? deg[i] : 0;
    __syncthreads();
    #pragma unroll
    for (int o = SCAN_B / 2; o > 0; o >>= 1) {
        if (tid < o) s[tid] += s[tid + o];
        __syncthreads();
    }
    if (tid == 0) bsum[blockIdx.x] = s[0];
}

// ---------------------------------------------------------------------------
// CSR step 2b: exclusive scan of block sums (tiny, one block)
// ---------------------------------------------------------------------------
__global__ __launch_bounds__(64) void scanB_kernel(int* __restrict__ bsum, int nb) {
    __shared__ int s[64];
    int tid = threadIdx.x;
    int v = (tid < nb) ? bsum[tid] : 0;
    s[tid] = v;
    __syncthreads();
    #pragma unroll
    for (int o = 1; o < 64; o <<= 1) {
        int t = (tid >= o) ? s[tid - o] : 0;
        __syncthreads();
        s[tid] += t;
        __syncthreads();
    }
    if (tid < nb) bsum[tid] = s[tid] - v;
}

// ---------------------------------------------------------------------------
// CSR step 2c: per-element offsets
// ---------------------------------------------------------------------------
__global__ __launch_bounds__(SCAN_B) void scanC_kernel(
    const int* __restrict__ deg, const int* __restrict__ bsum,
    int* __restrict__ off, int* __restrict__ cur, int n) {
    __shared__ int s[SCAN_B];
    int tid = threadIdx.x;
    int i = blockIdx.x * SCAN_B + tid;
    int v = (i < n) ? deg[i] : 0;
    s[tid] = v;
    __syncthreads();
    #pragma unroll
    for (int o = 1; o < SCAN_B; o <<= 1) {
        int t = (tid >= o) ? s[tid - o] : 0;
        __syncthreads();
        s[tid] += t;
        __syncthreads();
    }
    int ex = bsum[blockIdx.x] + s[tid] - v;
    if (i < n) { off[i] = ex; cur[i] = ex; }
    if (i == n - 1) off[n] = ex + v;
}

// ---------------------------------------------------------------------------
// CSR step 3: fill
// ---------------------------------------------------------------------------
__global__ void fill_kernel(const int* __restrict__ src,
                            const int* __restrict__ dst,
                            int* __restrict__ cur, int* __restrict__ eidx,
                            int n_edges) {
    int i = blockIdx.x * blockDim.x + threadIdx.x;
    if (i < n_edges) {
        int p = atomicAdd(cur + __ldg(dst + i), 1);
        eidx[p] = __ldg(src + i);
    }
}

// ---------------------------------------------------------------------------
// fp16 gather: one warp per node, 8 lanes per edge row (8 x float4 = 64
// halves), 4 edges per LDG warp-instruction, 4-deep predicated unroll
// (16 edges in flight). Accumulate fp32, write agg fp32.
// ---------------------------------------------------------------------------
__device__ __forceinline__ void acc8(float* acc, float4 u, float m) {
    __half2* p = reinterpret_cast<__half2*>(&u);
    #pragma unroll
    for (int k = 0; k < 4; k++) {
        float2 f = __half22float2(p[k]);
        acc[2 * k]     += m * f.x;
        acc[2 * k + 1] += m * f.y;
    }
}

__global__ __launch_bounds__(256) void gather_h_kernel(
    const float4* __restrict__ hv,   // fp16 table viewed as float4 (8/row)
    const int* __restrict__ eidx,
    const int* __restrict__ off, float* __restrict__ agg, int n) {
    int warp = (blockIdx.x * blockDim.x + threadIdx.x) >> 5;
    if (warp >= n) return;
    int lane = threadIdx.x & 31;
    int q    = lane >> 3;      // 0..3: which edge within the group of 4
    int hl   = lane & 7;       // 0..7: float4 within row
    int o    = __ldg(off + warp);
    int e    = __ldg(off + warp + 1);
    int last = max(o, e - 1);

    float acc[8] = {0.f, 0.f, 0.f, 0.f, 0.f, 0.f, 0.f, 0.f};
    for (int i = o + q; i < e; i += 16) {
        int j1 = i + 4, j2 = i + 8, j3 = i + 12;
        int s0 = __ldg(eidx + i);
        int s1 = __ldg(eidx + min(j1, last));
        int s2 = __ldg(eidx + min(j2, last));
        int s3 = __ldg(eidx + min(j3, last));
        float m1 = (j1 < e) ? 1.f : 0.f;
        float m2 = (j2 < e) ? 1.f : 0.f;
        float m3 = (j3 < e) ? 1.f : 0.f;
        float4 u0 = __ldg(hv + (size_t)s0 * 8 + hl);
        float4 u1 = __ldg(hv + (size_t)s1 * 8 + hl);
        float4 u2 = __ldg(hv + (size_t)s2 * 8 + hl);
        float4 u3 = __ldg(hv + (size_t)s3 * 8 + hl);
        acc8(acc, u0, 1.f);
        acc8(acc, u1, m1);
        acc8(acc, u2, m2);
        acc8(acc, u3, m3);
    }
    #pragma unroll
    for (int k = 0; k < 8; k++) {
        acc[k] += __shfl_down_sync(0xffffffffu, acc[k], 16);
        acc[k] += __shfl_down_sync(0xffffffffu, acc[k], 8);
    }
    if (q == 0) {
        float4* out = reinterpret_cast<float4*>(agg + (size_t)warp * D + hl * 8);
        out[0] = make_float4(acc[0], acc[1], acc[2], acc[3]);
        out[1] = make_float4(acc[4], acc[5], acc[6], acc[7]);
    }
}

// ---------------------------------------------------------------------------
// Y(fp16) = relu(X @ W + b). Thread-per-row, W broadcast from smem.
// ---------------------------------------------------------------------------
__global__ __launch_bounds__(256) void gemm_relu_h_kernel(
    const float* __restrict__ X, const float* __restrict__ W,
    const float* __restrict__ b, uint2* __restrict__ Yh, int n) {
    __shared__ float4 Ws[D * 16];
    __shared__ float  bs[D];
    int tid = threadIdx.x;
    for (int i = tid; i < D * 16; i += 256) Ws[i] = reinterpret_cast<const float4*>(W)[i];
    if (tid < D) bs[tid] = b[tid];
    __syncthreads();

    int row = blockIdx.x * 256 + tid;
    if (row >= n) return;
    const float4* xr = reinterpret_cast<const float4*>(X + (size_t)row * D);

    float4 acc[16];
    #pragma unroll
    for (int j = 0; j < 16; j++) acc[j] = reinterpret_cast<const float4*>(bs)[j];

    #pragma unroll 4
    for (int kc = 0; kc < 16; kc++) {
        float4 x = xr[kc];
        int kb = kc * 4;
        #pragma unroll
        for (int j = 0; j < 16; j++) {
            float4 a = acc[j];
            float4 w;
            w = Ws[(kb + 0) * 16 + j];
            a.x += x.x * w.x; a.y += x.x * w.y; a.z += x.x * w.z; a.w += x.x * w.w;
            w = Ws[(kb + 1) * 16 + j];
            a.x += x.y * w.x; a.y += x.y * w.y; a.z += x.y * w.z; a.w += x.y * w.w;
            w = Ws[(kb + 2) * 16 + j];
            a.x += x.z * w.x; a.y += x.z * w.y; a.z += x.z * w.z; a.w += x.z * w.w;
            w = Ws[(kb + 3) * 16 + j];
            a.x += x.w * w.x; a.y += x.w * w.y; a.z += x.w * w.z; a.w += x.w * w.w;
            acc[j] = a;
        }
    }

    uint2* yr = Yh + (size_t)row * 16;
    #pragma unroll
    for (int j = 0; j < 16; j++) {
        float4 a = acc[j];
        __half2 p0 = __floats2half2_rn(fmaxf(a.x, 0.f), fmaxf(a.y, 0.f));
        __half2 p1 = __floats2half2_rn(fmaxf(a.z, 0.f), fmaxf(a.w, 0.f));
        uint2 o;
        o.x = *(unsigned*)&p0;
        o.y = *(unsigned*)&p1;
        yr[j] = o;
    }
}

// ---------------------------------------------------------------------------
// Layer-2 GEMM + relu + both heads fused (fp32 in, fp32 out).
// ---------------------------------------------------------------------------
__global__ __launch_bounds__(256) void gemm_heads_kernel(
    const float* __restrict__ X, const float* __restrict__ W,
    const float* __restrict__ b,
    const float* __restrict__ Wa, const float* __restrict__ ba,
    const float* __restrict__ Wb, const float* __restrict__ bb,
    float* __restrict__ xa_out, float* __restrict__ xb_out, int n) {
    __shared__ float4 Ws[D * 16];
    __shared__ float  bs[D];
    __shared__ float  Was[D * 2];
    __shared__ float  Wbs[D * 16];
    __shared__ float  bas[2];
    __shared__ float  bbs[16];
    int tid = threadIdx.x;
    for (int i = tid; i < D * 16; i += 256) Ws[i] = reinterpret_cast<const float4*>(W)[i];
    for (int i = tid; i < D * 16; i += 256) Wbs[i] = Wb[i];
    if (tid < D * 2) Was[tid] = Wa[tid];
    if (tid < D) bs[tid] = b[tid];
    if (tid < 2) bas[tid] = ba[tid];
    if (tid < 16) bbs[tid] = bb[tid];
    __syncthreads();

    int row = blockIdx.x * 256 + tid;
    if (row >= n) return;
    const float4* xr = reinterpret_cast<const float4*>(X + (size_t)row * D);

    float4 acc[16];
    #pragma unroll
    for (int j = 0; j < 16; j++) acc[j] = reinterpret_cast<const float4*>(bs)[j];

    #pragma unroll 4
    for (int kc = 0; kc < 16; kc++) {
        float4 x = xr[kc];
        int kb = kc * 4;
        #pragma unroll
        for (int j = 0; j < 16; j++) {
            float4 a = acc[j];
            float4 w;
            w = Ws[(kb + 0) * 16 + j];
            a.x += x.x * w.x; a.y += x.x * w.y; a.z += x.x * w.z; a.w += x.x * w.w;
            w = Ws[(kb + 1) * 16 + j];
            a.x += x.y * w.x; a.y += x.y * w.y; a.z += x.y * w.z; a.w += x.y * w.w;
            w = Ws[(kb + 2) * 16 + j];
            a.x += x.z * w.x; a.y += x.z * w.y; a.z += x.z * w.z; a.w += x.z * w.w;
            w = Ws[(kb + 3) * 16 + j];
            a.x += x.w * w.x; a.y += x.w * w.y; a.z += x.w * w.z; a.w += x.w * w.w;
            acc[j] = a;
        }
    }

    float h[D];
    #pragma unroll
    for (int j = 0; j < 16; j++) {
        h[4*j+0] = fmaxf(acc[j].x, 0.f);
        h[4*j+1] = fmaxf(acc[j].y, 0.f);
        h[4*j+2] = fmaxf(acc[j].z, 0.f);
        h[4*j+3] = fmaxf(acc[j].w, 0.f);
    }

    float a0 = bas[0], a1 = bas[1];
    #pragma unroll
    for (int j = 0; j < D; j++) {
        a0 += h[j] * Was[j * 2 + 0];
        a1 += h[j] * Was[j * 2 + 1];
    }
    xa_out[(size_t)row * 2 + 0] = a0;
    xa_out[(size_t)row * 2 + 1] = a1;

    float hb[16];
    #pragma unroll
    for (int t = 0; t < 16; t++) hb[t] = bbs[t];
    #pragma unroll
    for (int j = 0; j < D; j++) {
        float hv = h[j];
        #pragma unroll
        for (int t = 0; t < 16; t++) hb[t] += hv * Wbs[j * 16 + t];
    }
    float4* out4 = reinterpret_cast<float4*>(xb_out + (size_t)row * 16);
    #pragma unroll
    for (int q = 0; q < 4; q++)
        out4[q] = make_float4(hb[4*q+0], hb[4*q+1], hb[4*q+2], hb[4*q+3]);
}

// ---------------------------------------------------------------------------
extern "C" void kernel_launch(void* const* d_in, const int* in_sizes, int n_in,
                              void* d_out, int out_size) {
    const float* v   = (const float*)d_in[0];
    const int*   src = (const int*)  d_in[1];
    const int*   dst = (const int*)  d_in[2];
    const float* W1  = (const float*)d_in[3];
    const float* b1  = (const float*)d_in[4];
    const float* W2  = (const float*)d_in[5];
    const float* b2  = (const float*)d_in[6];
    const float* Wa  = (const float*)d_in[7];
    const float* ba  = (const float*)d_in[8];
    const float* Wb  = (const float*)d_in[9];
    const float* bb  = (const float*)d_in[10];

    int n_nodes = in_sizes[0] / D;
    int n_edges = in_sizes[1];

    float*  agg;  cudaGetSymbolAddress((void**)&agg,  g_agg);
    __half* h1;   cudaGetSymbolAddress((void**)&h1,   g_h1);
    __half* vh;   cudaGetSymbolAddress((void**)&vh,   g_vh);
    int*    deg;  cudaGetSymbolAddress((void**)&deg,  g_deg);
    int*    off;  cudaGetSymbolAddress((void**)&off,  g_off);
    int*    cur;  cudaGetSymbolAddress((void**)&cur,  g_cur);
    int*    eidx; cudaGetSymbolAddress((void**)&eidx, g_eidx);
    int*    bsum; cudaGetSymbolAddress((void**)&bsum, g_bsum);

    float* xa_out = (float*)d_out;
    float* xb_out = (float*)d_out + (size_t)n_nodes * 2;

    int nconv = n_nodes * D / 4;
    int conv_blocks   = (nconv + 255) / 256;
    int edge_blocks   = (n_edges + 255) / 256;
    int scan_blocks   = (n_nodes + SCAN_B - 1) / SCAN_B;
    int gather_blocks = (n_nodes * 32 + 255) / 256;
    int gemm_blocks   = (n_nodes + 255) / 256;

    // ---- CSR build + fp16 conversion ----
    cudaMemsetAsync(deg, 0, n_nodes * sizeof(int));
    hist_conv_kernel<<<conv_blocks + edge_blocks, 256>>>(
        dst, deg, n_edges, (const float4*)v, (uint2*)vh, nconv, conv_blocks);
    scanA_kernel<<<scan_blocks, SCAN_B>>>(deg, bsum, n_nodes);
    scanB_kernel<<<1, 64>>>(bsum, scan_blocks);
    scanC_kernel<<<scan_blocks, SCAN_B>>>(deg, bsum, off, cur, n_nodes);
    fill_kernel <<<edge_blocks, 256>>>(src, dst, cur, eidx, n_edges);

    // ---- Layer 1 ----
    gather_h_kernel<<<gather_blocks, 256>>>((const float4*)vh, eidx, off, agg, n_nodes);
    gemm_relu_h_kernel<<<gemm_blocks, 256>>>(agg, W1, b1, (uint2*)h1, n_nodes);

    // ---- Layer 2 + heads ----
    gather_h_kernel<<<gather_blocks, 256>>>((const float4*)h1, eidx, off, agg, n_nodes);
    gemm_heads_kernel<<<gemm_blocks, 256>>>(agg, W2, b2, Wa, ba, Wb, bb,
                                            xa_out, xb_out, n_nodes);
}

// round 12
// speedup vs baseline: 1.2267x; 1.1102x over previous
#include <cuda_runtime.h>
#include <cuda_bf16.h>

#define N_NODES_MAX 50000
#define N_EDGES_MAX 800000
#define D 64
#define SCAN_B 1024

// Scratch (no cudaMalloc allowed). BSS-zeroed at load; fill_kernel re-zeros
// deg at the end of every call, so hist always sees zeros.
__device__ float g_h1  [N_NODES_MAX * D];
__device__ float g_agg [N_NODES_MAX * D];
__device__ int   g_deg [N_NODES_MAX];
__device__ int   g_off [N_NODES_MAX + 1];
__device__ int   g_cur [N_NODES_MAX];
__device__ int   g_eidx[N_EDGES_MAX];

// ---------------------------------------------------------------------------
// CSR step 1: histogram of dst (deg is pre-zeroed by previous call's fill)
// ---------------------------------------------------------------------------
__global__ void hist_kernel(const int* __restrict__ dst, int* __restrict__ deg,
                            int n_edges) {
    int i = blockIdx.x * blockDim.x + threadIdx.x;
    if (i < n_edges) atomicAdd(deg + __ldg(dst + i), 1);
}

// ---------------------------------------------------------------------------
// CSR step 2 (single kernel): block bid computes base = sum(deg[0..bid*1024))
// directly (coalesced, L2-resident), then shuffle-scans its own tile.
// ---------------------------------------------------------------------------
__global__ __launch_bounds__(SCAN_B) void scan_kernel(
    const int* __restrict__ deg, int* __restrict__ off,
    int* __restrict__ cur, int n) {
    __shared__ int wsum[32];
    __shared__ int sbase;
    int tid  = threadIdx.x;
    int bid  = blockIdx.x;
    int lane = tid & 31, w = tid >> 5;

    // ---- phase 1: base = sum of all preceding tiles ----
    int lim = bid * SCAN_B;
    int s = 0;
    for (int j = tid; j < lim; j += SCAN_B) s += deg[j];
    #pragma unroll
    for (int o = 16; o > 0; o >>= 1)
        s += __shfl_down_sync(0xffffffffu, s, o);
    if (lane == 0) wsum[w] = s;
    __syncthreads();
    if (w == 0) {
        int t = wsum[lane];
        #pragma unroll
        for (int o = 16; o > 0; o >>= 1)
            t += __shfl_down_sync(0xffffffffu, t, o);
        if (lane == 0) sbase = t;
    }
    __syncthreads();
    int base = sbase;
    __syncthreads();           // wsum reuse below

    // ---- phase 2: shuffle scan of own tile ----
    int i = bid * SCAN_B + tid;
    int v = (i < n) ? deg[i] : 0;
    int x = v;
    #pragma unroll
    for (int o = 1; o < 32; o <<= 1) {
        int t = __shfl_up_sync(0xffffffffu, x, o);
        if (lane >= o) x += t;
    }
    if (lane == 31) wsum[w] = x;
    __syncthreads();
    if (w == 0) {
        int y = wsum[lane];
        #pragma unroll
        for (int o = 1; o < 32; o <<= 1) {
            int t = __shfl_up_sync(0xffffffffu, y, o);
            if (lane >= o) y += t;
        }
        wsum[lane] = y;
    }
    __syncthreads();
    int incl = x + ((w > 0) ? wsum[w - 1] : 0);
    int ex = base + incl - v;
    if (i < n) { off[i] = ex; cur[i] = ex; }
    if (i == n - 1) off[n] = ex + v;
}

// ---------------------------------------------------------------------------
// CSR step 3: fill — claim slot per edge, record src node.
// Tail: re-zero deg so the NEXT kernel_launch call starts clean (removes the
// memset node). deg is dead after scan_kernel within this call.
// ---------------------------------------------------------------------------
__global__ void fill_kernel(const int* __restrict__ src,
                            const int* __restrict__ dst,
                            int* __restrict__ cur, int* __restrict__ eidx,
                            int* __restrict__ deg,
                            int n_edges, int n_nodes) {
    int i = blockIdx.x * blockDim.x + threadIdx.x;
    if (i < n_edges) {
        int p = atomicAdd(cur + __ldg(dst + i), 1);
        eidx[p] = __ldg(src + i);
    }
    if (i < n_nodes) deg[i] = 0;
}

// ---------------------------------------------------------------------------
// Gather (R7-proven): one warp per node; half-warp per edge (16 x float4).
// Fully predicated, 4 loads in flight per half-warp.
// ---------------------------------------------------------------------------
__global__ __launch_bounds__(256) void gather_kernel(
    const float* __restrict__ h, const int* __restrict__ eidx,
    const int* __restrict__ off, float* __restrict__ agg, int n) {
    int warp = (blockIdx.x * blockDim.x + threadIdx.x) >> 5;
    if (warp >= n) return;
    int lane = threadIdx.x & 31;
    int half = lane >> 4;
    int hl   = lane & 15;
    int o    = __ldg(off + warp);
    int e    = __ldg(off + warp + 1);
    int last = max(o, e - 1);

    float4 acc = make_float4(0.f, 0.f, 0.f, 0.f);
    for (int i = o + half; i < e; i += 8) {
        int j1 = i + 2, j2 = i + 4, j3 = i + 6;
        int s0 = __ldg(eidx + i);
        int s1 = __ldg(eidx + min(j1, last));
        int s2 = __ldg(eidx + min(j2, last));
        int s3 = __ldg(eidx + min(j3, last));
        float m1 = (j1 < e) ? 1.f : 0.f;
        float m2 = (j2 < e) ? 1.f : 0.f;
        float m3 = (j3 < e) ? 1.f : 0.f;
        float4 v0 = *reinterpret_cast<const float4*>(h + (size_t)s0 * D + hl * 4);
        float4 v1 = *reinterpret_cast<const float4*>(h + (size_t)s1 * D + hl * 4);
        float4 v2 = *reinterpret_cast<const float4*>(h + (size_t)s2 * D + hl * 4);
        float4 v3 = *reinterpret_cast<const float4*>(h + (size_t)s3 * D + hl * 4);
        acc.x += v0.x + m1 * v1.x + m2 * v2.x + m3 * v3.x;
        acc.y += v0.y + m1 * v1.y + m2 * v2.y + m3 * v3.y;
        acc.z += v0.z + m1 * v1.z + m2 * v2.z + m3 * v3.z;
        acc.w += v0.w + m1 * v1.w + m2 * v2.w + m3 * v3.w;
    }
    acc.x += __shfl_down_sync(0xffffffffu, acc.x, 16);
    acc.y += __shfl_down_sync(0xffffffffu, acc.y, 16);
    acc.z += __shfl_down_sync(0xffffffffu, acc.z, 16);
    acc.w += __shfl_down_sync(0xffffffffu, acc.w, 16);
    if (half == 0)
        *reinterpret_cast<float4*>(agg + (size_t)warp * D + hl * 4) = acc;
}

// ---------------------------------------------------------------------------
// Y = relu(X @ W + b). Thread-per-row, W broadcast from smem. (R7-proven)
// ---------------------------------------------------------------------------
__global__ __launch_bounds__(256) void gemm_relu_kernel(
    const float* __restrict__ X, const float* __restrict__ W,
    const float* __restrict__ b, float* __restrict__ Y, int n) {
    __shared__ float4 Ws[D * 16];
    __shared__ float  bs[D];
    int tid = threadIdx.x;
    for (int i = tid; i < D * 16; i += 256) Ws[i] = reinterpret_cast<const float4*>(W)[i];
    if (tid < D) bs[tid] = b[tid];
    __syncthreads();

    int row = blockIdx.x * 256 + tid;
    if (row >= n) return;
    const float4* xr = reinterpret_cast<const float4*>(X + (size_t)row * D);

    float4 acc[16];
    #pragma unroll
    for (int j = 0; j < 16; j++) acc[j] = reinterpret_cast<const float4*>(bs)[j];

    #pragma unroll 4
    for (int kc = 0; kc < 16; kc++) {
        float4 x = xr[kc];
        int kb = kc * 4;
        #pragma unroll
        for (int j = 0; j < 16; j++) {
            float4 a = acc[j];
            float4 w;
            w = Ws[(kb + 0) * 16 + j];
            a.x += x.x * w.x; a.y += x.x * w.y; a.z += x.x * w.z; a.w += x.x * w.w;
            w = Ws[(kb + 1) * 16 + j];
            a.x += x.y * w.x; a.y += x.y * w.y; a.z += x.y * w.z; a.w += x.y * w.w;
            w = Ws[(kb + 2) * 16 + j];
            a.x += x.z * w.x; a.y += x.z * w.y; a.z += x.z * w.z; a.w += x.z * w.w;
            w = Ws[(kb + 3) * 16 + j];
            a.x += x.w * w.x; a.y += x.w * w.y; a.z += x.w * w.z; a.w += x.w * w.w;
            acc[j] = a;
        }
    }

    float4* yr = reinterpret_cast<float4*>(Y + (size_t)row * D);
    #pragma unroll
    for (int j = 0; j < 16; j++) {
        float4 a = acc[j];
        a.x = fmaxf(a.x, 0.f); a.y = fmaxf(a.y, 0.f);
        a.z = fmaxf(a.z, 0.f); a.w = fmaxf(a.w, 0.f);
        yr[j] = a;
    }
}

// ---------------------------------------------------------------------------
// Layer-2 GEMM + relu + both heads fused. (R7-proven)
// ---------------------------------------------------------------------------
__global__ __launch_bounds__(256) void gemm_heads_kernel(
    const float* __restrict__ X, const float* __restrict__ W,
    const float* __restrict__ b,
    const float* __restrict__ Wa, const float* __restrict__ ba,
    const float* __restrict__ Wb, const float* __restrict__ bb,
    float* __restrict__ xa_out, float* __restrict__ xb_out, int n) {
    __shared__ float4 Ws[D * 16];
    __shared__ float  bs[D];
    __shared__ float  Was[D * 2];
    __shared__ float  Wbs[D * 16];
    __shared__ float  bas[2];
    __shared__ float  bbs[16];
    int tid = threadIdx.x;
    for (int i = tid; i < D * 16; i += 256) Ws[i] = reinterpret_cast<const float4*>(W)[i];
    for (int i = tid; i < D * 16; i += 256) Wbs[i] = Wb[i];
    if (tid < D * 2) Was[tid] = Wa[tid];
    if (tid < D) bs[tid] = b[tid];
    if (tid < 2) bas[tid] = ba[tid];
    if (tid < 16) bbs[tid] = bb[tid];
    __syncthreads();

    int row = blockIdx.x * 256 + tid;
    if (row >= n) return;
    const float4* xr = reinterpret_cast<const float4*>(X + (size_t)row * D);

    float4 acc[16];
    #pragma unroll
    for (int j = 0; j < 16; j++) acc[j] = reinterpret_cast<const float4*>(bs)[j];

    #pragma unroll 4
    for (int kc = 0; kc < 16; kc++) {
        float4 x = xr[kc];
        int kb = kc * 4;
        #pragma unroll
        for (int j = 0; j < 16; j++) {
            float4 a = acc[j];
            float4 w;
            w = Ws[(kb + 0) * 16 + j];
            a.x += x.x * w.x; a.y += x.x * w.y; a.z += x.x * w.z; a.w += x.x * w.w;
            w = Ws[(kb + 1) * 16 + j];
            a.x += x.y * w.x; a.y += x.y * w.y; a.z += x.y * w.z; a.w += x.y * w.w;
            w = Ws[(kb + 2) * 16 + j];
            a.x += x.z * w.x; a.y += x.z * w.y; a.z += x.z * w.z; a.w += x.z * w.w;
            w = Ws[(kb + 3) * 16 + j];
            a.x += x.w * w.x; a.y += x.w * w.y; a.z += x.w * w.z; a.w += x.w * w.w;
            acc[j] = a;
        }
    }

    float h[D];
    #pragma unroll
    for (int j = 0; j < 16; j++) {
        h[4*j+0] = fmaxf(acc[j].x, 0.f);
        h[4*j+1] = fmaxf(acc[j].y, 0.f);
        h[4*j+2] = fmaxf(acc[j].z, 0.f);
        h[4*j+3] = fmaxf(acc[j].w, 0.f);
    }

    float a0 = bas[0], a1 = bas[1];
    #pragma unroll
    for (int j = 0; j < D; j++) {
        a0 += h[j] * Was[j * 2 + 0];
        a1 += h[j] * Was[j * 2 + 1];
    }
    xa_out[(size_t)row * 2 + 0] = a0;
    xa_out[(size_t)row * 2 + 1] = a1;

    float hb[16];
    #pragma unroll
    for (int t = 0; t < 16; t++) hb[t] = bbs[t];
    #pragma unroll
    for (int j = 0; j < D; j++) {
        float hv = h[j];
        #pragma unroll
        for (int t = 0; t < 16; t++) hb[t] += hv * Wbs[j * 16 + t];
    }
    float4* out4 = reinterpret_cast<float4*>(xb_out + (size_t)row * 16);
    #pragma unroll
    for (int q = 0; q < 4; q++)
        out4[q] = make_float4(hb[4*q+0], hb[4*q+1], hb[4*q+2], hb[4*q+3]);
}

// ---------------------------------------------------------------------------
extern "C" void kernel_launch(void* const* d_in, const int* in_sizes, int n_in,
                              void* d_out, int out_size) {
    const float* v   = (const float*)d_in[0];
    const int*   src = (const int*)  d_in[1];
    const int*   dst = (const int*)  d_in[2];
    const float* W1  = (const float*)d_in[3];
    const float* b1  = (const float*)d_in[4];
    const float* W2  = (const float*)d_in[5];
    const float* b2  = (const float*)d_in[6];
    const float* Wa  = (const float*)d_in[7];
    const float* ba  = (const float*)d_in[8];
    const float* Wb  = (const float*)d_in[9];
    const float* bb  = (const float*)d_in[10];

    int n_nodes = in_sizes[0] / D;
    int n_edges = in_sizes[1];

    float* agg;  cudaGetSymbolAddress((void**)&agg,  g_agg);
    float* h1;   cudaGetSymbolAddress((void**)&h1,   g_h1);
    int*   deg;  cudaGetSymbolAddress((void**)&deg,  g_deg);
    int*   off;  cudaGetSymbolAddress((void**)&off,  g_off);
    int*   cur;  cudaGetSymbolAddress((void**)&cur,  g_cur);
    int*   eidx; cudaGetSymbolAddress((void**)&eidx, g_eidx);

    float* xa_out = (float*)d_out;
    float* xb_out = (float*)d_out + (size_t)n_nodes * 2;

    int edge_blocks   = (n_edges + 255) / 256;
    int scan_blocks   = (n_nodes + SCAN_B - 1) / SCAN_B;
    int gather_blocks = (n_nodes * 32 + 255) / 256;
    int gemm_blocks   = (n_nodes + 255) / 256;

    // ---- CSR build (deg already zero: BSS on call 1, fill's tail after) ----
    hist_kernel<<<edge_blocks, 256>>>(dst, deg, n_edges);
    scan_kernel<<<scan_blocks, SCAN_B>>>(deg, off, cur, n_nodes);
    fill_kernel<<<edge_blocks, 256>>>(src, dst, cur, eidx, deg,
                                      n_edges, n_nodes);

    // ---- Layer 1 ----
    gather_kernel<<<gather_blocks, 256>>>(v, eidx, off, agg, n_nodes);
    gemm_relu_kernel<<<gemm_blocks, 256>>>(agg, W1, b1, h1, n_nodes);

    // ---- Layer 2 + heads ----
    gather_kernel<<<gather_blocks, 256>>>(h1, eidx, off, agg, n_nodes);
    gemm_heads_kernel<<<gemm_blocks, 256>>>(agg, W2, b2, Wa, ba, Wb, bb,
                                            xa_out, xb_out, n_nodes);
}

// round 13
// speedup vs baseline: 1.7502x; 1.4267x over previous
#include <cuda_runtime.h>
#include <cuda_fp16.h>
#include <mma.h>

using namespace nvcuda;

#define N_NODES_MAX 50000
#define N_EDGES_MAX 800000
#define D 64
#define SCAN_B 1024

// Scratch (no cudaMalloc allowed). BSS-zeroed at load; fill_kernel re-zeros
// deg at the end of every call, so hist always sees zeros.
__device__ float g_h1  [N_NODES_MAX * D];
__device__ float g_agg [N_NODES_MAX * D];
__device__ int   g_deg [N_NODES_MAX];
__device__ int   g_off [N_NODES_MAX + 1];
__device__ int   g_cur [N_NODES_MAX];
__device__ int   g_eidx[N_EDGES_MAX];

// ---------------------------------------------------------------------------
// CSR step 1: histogram of dst (deg pre-zeroed by previous call's fill)
// ---------------------------------------------------------------------------
__global__ void hist_kernel(const int* __restrict__ dst, int* __restrict__ deg,
                            int n_edges) {
    int i = blockIdx.x * blockDim.x + threadIdx.x;
    if (i < n_edges) atomicAdd(deg + __ldg(dst + i), 1);
}

// ---------------------------------------------------------------------------
// CSR step 2: single-kernel scan (direct base sum + tile shuffle scan)
// ---------------------------------------------------------------------------
__global__ __launch_bounds__(SCAN_B) void scan_kernel(
    const int* __restrict__ deg, int* __restrict__ off,
    int* __restrict__ cur, int n) {
    __shared__ int wsum[32];
    __shared__ int sbase;
    int tid  = threadIdx.x;
    int bid  = blockIdx.x;
    int lane = tid & 31, w = tid >> 5;

    int lim = bid * SCAN_B;
    int s = 0;
    for (int j = tid; j < lim; j += SCAN_B) s += deg[j];
    #pragma unroll
    for (int o = 16; o > 0; o >>= 1)
        s += __shfl_down_sync(0xffffffffu, s, o);
    if (lane == 0) wsum[w] = s;
    __syncthreads();
    if (w == 0) {
        int t = wsum[lane];
        #pragma unroll
        for (int o = 16; o > 0; o >>= 1)
            t += __shfl_down_sync(0xffffffffu, t, o);
        if (lane == 0) sbase = t;
    }
    __syncthreads();
    int base = sbase;
    __syncthreads();

    int i = bid * SCAN_B + tid;
    int v = (i < n) ? deg[i] : 0;
    int x = v;
    #pragma unroll
    for (int o = 1; o < 32; o <<= 1) {
        int t = __shfl_up_sync(0xffffffffu, x, o);
        if (lane >= o) x += t;
    }
    if (lane == 31) wsum[w] = x;
    __syncthreads();
    if (w == 0) {
        int y = wsum[lane];
        #pragma unroll
        for (int o = 1; o < 32; o <<= 1) {
            int t = __shfl_up_sync(0xffffffffu, y, o);
            if (lane >= o) y += t;
        }
        wsum[lane] = y;
    }
    __syncthreads();
    int incl = x + ((w > 0) ? wsum[w - 1] : 0);
    int ex = base + incl - v;
    if (i < n) { off[i] = ex; cur[i] = ex; }
    if (i == n - 1) off[n] = ex + v;
}

// ---------------------------------------------------------------------------
// CSR step 3: fill + tail deg-rezero
// ---------------------------------------------------------------------------
__global__ void fill_kernel(const int* __restrict__ src,
                            const int* __restrict__ dst,
                            int* __restrict__ cur, int* __restrict__ eidx,
                            int* __restrict__ deg,
                            int n_edges, int n_nodes) {
    int i = blockIdx.x * blockDim.x + threadIdx.x;
    if (i < n_edges) {
        int p = atomicAdd(cur + __ldg(dst + i), 1);
        eidx[p] = __ldg(src + i);
    }
    if (i < n_nodes) deg[i] = 0;
}

// ---------------------------------------------------------------------------
// Gather (R7/R12-proven): warp per node; half-warp per edge (16 x float4).
// ---------------------------------------------------------------------------
__global__ __launch_bounds__(256) void gather_kernel(
    const float* __restrict__ h, const int* __restrict__ eidx,
    const int* __restrict__ off, float* __restrict__ agg, int n) {
    int warp = (blockIdx.x * blockDim.x + threadIdx.x) >> 5;
    if (warp >= n) return;
    int lane = threadIdx.x & 31;
    int half = lane >> 4;
    int hl   = lane & 15;
    int o    = __ldg(off + warp);
    int e    = __ldg(off + warp + 1);
    int last = max(o, e - 1);

    float4 acc = make_float4(0.f, 0.f, 0.f, 0.f);
    for (int i = o + half; i < e; i += 8) {
        int j1 = i + 2, j2 = i + 4, j3 = i + 6;
        int s0 = __ldg(eidx + i);
        int s1 = __ldg(eidx + min(j1, last));
        int s2 = __ldg(eidx + min(j2, last));
        int s3 = __ldg(eidx + min(j3, last));
        float m1 = (j1 < e) ? 1.f : 0.f;
        float m2 = (j2 < e) ? 1.f : 0.f;
        float m3 = (j3 < e) ? 1.f : 0.f;
        float4 v0 = *reinterpret_cast<const float4*>(h + (size_t)s0 * D + hl * 4);
        float4 v1 = *reinterpret_cast<const float4*>(h + (size_t)s1 * D + hl * 4);
        float4 v2 = *reinterpret_cast<const float4*>(h + (size_t)s2 * D + hl * 4);
        float4 v3 = *reinterpret_cast<const float4*>(h + (size_t)s3 * D + hl * 4);
        acc.x += v0.x + m1 * v1.x + m2 * v2.x + m3 * v3.x;
        acc.y += v0.y + m1 * v1.y + m2 * v2.y + m3 * v3.y;
        acc.z += v0.z + m1 * v1.z + m2 * v2.z + m3 * v3.z;
        acc.w += v0.w + m1 * v1.w + m2 * v2.w + m3 * v3.w;
    }
    acc.x += __shfl_down_sync(0xffffffffu, acc.x, 16);
    acc.y += __shfl_down_sync(0xffffffffu, acc.y, 16);
    acc.z += __shfl_down_sync(0xffffffffu, acc.z, 16);
    acc.w += __shfl_down_sync(0xffffffffu, acc.w, 16);
    if (half == 0)
        *reinterpret_cast<float4*>(agg + (size_t)warp * D + hl * 4) = acc;
}

// ---------------------------------------------------------------------------
// Shared helper: stage a 128x64 fp32 tile into fp16 smem (zero-padded rows)
// ---------------------------------------------------------------------------
__device__ __forceinline__ void stage_tile_f16(
    const float* __restrict__ X, int base, int n, int tid,
    __half (*Xs)[72]) {
    for (int i = tid; i < 128 * 16; i += 256) {
        int r = i >> 4, c4 = i & 15;
        float4 xv = (base + r < n)
            ? *reinterpret_cast<const float4*>(X + (size_t)(base + r) * D + c4 * 4)
            : make_float4(0.f, 0.f, 0.f, 0.f);
        __half2* p = reinterpret_cast<__half2*>(&Xs[r][c4 * 4]);
        p[0] = __floats2half2_rn(xv.x, xv.y);
        p[1] = __floats2half2_rn(xv.z, xv.w);
    }
}

// ---------------------------------------------------------------------------
// Layer-1 GEMM via WMMA: h1 = relu(agg @ W1 + b1), fp16 in, fp32 acc/out.
// 128 rows/block, warp w owns rows [16w, 16w+16).
// ---------------------------------------------------------------------------
__global__ __launch_bounds__(256) void gemm1_wmma(
    const float* __restrict__ X, const float* __restrict__ W,
    const float* __restrict__ b, float* __restrict__ Y, int n) {
    __shared__ __align__(16) __half Xs[128][72];
    __shared__ __align__(16) __half Ws[64][72];
    __shared__ __align__(16) float  stage[8][16][16];
    __shared__ float bs[64];
    int tid = threadIdx.x, wid = tid >> 5, lane = tid & 31;
    int base = blockIdx.x * 128;

    for (int i = tid; i < 64 * 64; i += 256)
        Ws[i >> 6][i & 63] = __float2half(W[i]);
    if (tid < 64) bs[tid] = b[tid];
    stage_tile_f16(X, base, n, tid, Xs);
    __syncthreads();

    int r0 = wid * 16;
    for (int nt = 0; nt < 4; nt++) {
        wmma::fragment<wmma::accumulator, 16, 16, 16, float> c;
        wmma::fill_fragment(c, 0.f);
        #pragma unroll
        for (int kt = 0; kt < 4; kt++) {
            wmma::fragment<wmma::matrix_a, 16, 16, 16, half, wmma::row_major> a;
            wmma::fragment<wmma::matrix_b, 16, 16, 16, half, wmma::row_major> bf;
            wmma::load_matrix_sync(a,  &Xs[r0][kt * 16], 72);
            wmma::load_matrix_sync(bf, &Ws[kt * 16][nt * 16], 72);
            wmma::mma_sync(c, a, bf, c);
        }
        wmma::store_matrix_sync(&stage[wid][0][0], c, 16, wmma::mem_row_major);
        __syncwarp();
        for (int i = lane; i < 256; i += 32) {
            int rr = i >> 4, cc = i & 15;
            int grow = base + r0 + rr;
            if (grow < n) {
                float vv = stage[wid][rr][cc] + bs[nt * 16 + cc];
                Y[(size_t)grow * D + nt * 16 + cc] = fmaxf(vv, 0.f);
            }
        }
        __syncwarp();
    }
}

// ---------------------------------------------------------------------------
// Layer-2 GEMM + heads via WMMA (dynamic smem).
// h2 = relu(agg @ W2 + b2) kept as fp16 in smem; heads = h2 @ [Wb|Wa|0pad].
// ---------------------------------------------------------------------------
struct S2 {
    __half Xs[128][72];
    __half Ws[64][72];
    __half Hs[128][72];
    __half Whs[64][40];
    float  stage[8][16][16];
    float  bs[64];
    float  bh[32];
};

__global__ __launch_bounds__(256) void gemm2_wmma(
    const float* __restrict__ X, const float* __restrict__ W,
    const float* __restrict__ b,
    const float* __restrict__ Wa, const float* __restrict__ ba,
    const float* __restrict__ Wb, const float* __restrict__ bb,
    float* __restrict__ xa_out, float* __restrict__ xb_out, int n) {
    extern __shared__ __align__(16) char smem2[];
    S2* s = reinterpret_cast<S2*>(smem2);
    int tid = threadIdx.x, wid = tid >> 5, lane = tid & 31;
    int base = blockIdx.x * 128;

    for (int i = tid; i < 64 * 64; i += 256)
        s->Ws[i >> 6][i & 63] = __float2half(W[i]);
    // combined heads: cols 0..15 = Wb, 16..17 = Wa, 18..31 = 0
    for (int i = tid; i < 64 * 32; i += 256) {
        int k = i >> 5, t = i & 31;
        float wv = (t < 16) ? Wb[k * 16 + t]
                 : (t < 18) ? Wa[k * 2 + (t - 16)] : 0.f;
        s->Whs[k][t] = __float2half(wv);
    }
    if (tid < 64) s->bs[tid] = b[tid];
    if (tid < 32) s->bh[tid] = (tid < 16) ? bb[tid]
                              : (tid < 18) ? ba[tid - 16] : 0.f;
    stage_tile_f16(X, base, n, tid, s->Xs);
    __syncthreads();

    int r0 = wid * 16;
    // h2 GEMM: 4 n-tiles -> relu -> fp16 into Hs (own rows only)
    for (int nt = 0; nt < 4; nt++) {
        wmma::fragment<wmma::accumulator, 16, 16, 16, float> c;
        wmma::fill_fragment(c, 0.f);
        #pragma unroll
        for (int kt = 0; kt < 4; kt++) {
            wmma::fragment<wmma::matrix_a, 16, 16, 16, half, wmma::row_major> a;
            wmma::fragment<wmma::matrix_b, 16, 16, 16, half, wmma::row_major> bf;
            wmma::load_matrix_sync(a,  &s->Xs[r0][kt * 16], 72);
            wmma::load_matrix_sync(bf, &s->Ws[kt * 16][nt * 16], 72);
            wmma::mma_sync(c, a, bf, c);
        }
        wmma::store_matrix_sync(&s->stage[wid][0][0], c, 16, wmma::mem_row_major);
        __syncwarp();
        for (int i = lane; i < 256; i += 32) {
            int rr = i >> 4, cc = i & 15;
            float vv = fmaxf(s->stage[wid][rr][cc] + s->bs[nt * 16 + cc], 0.f);
            s->Hs[r0 + rr][nt * 16 + cc] = __float2half(vv);
        }
        __syncwarp();
    }

    // heads: 2 n-tiles over [Wb|Wa|pad]
    for (int nt = 0; nt < 2; nt++) {
        wmma::fragment<wmma::accumulator, 16, 16, 16, float> c;
        wmma::fill_fragment(c, 0.f);
        #pragma unroll
        for (int kt = 0; kt < 4; kt++) {
            wmma::fragment<wmma::matrix_a, 16, 16, 16, half, wmma::row_major> a;
            wmma::fragment<wmma::matrix_b, 16, 16, 16, half, wmma::row_major> bf;
            wmma::load_matrix_sync(a,  &s->Hs[r0][kt * 16], 72);
            wmma::load_matrix_sync(bf, &s->Whs[kt * 16][nt * 16], 40);
            wmma::mma_sync(c, a, bf, c);
        }
        wmma::store_matrix_sync(&s->stage[wid][0][0], c, 16, wmma::mem_row_major);
        __syncwarp();
        for (int i = lane; i < 256; i += 32) {
            int rr = i >> 4, cc = i & 15;
            int t = nt * 16 + cc;
            int grow = base + r0 + rr;
            if (grow < n && t < 18) {
                float vv = s->stage[wid][rr][cc] + s->bh[t];
                if (t < 16) xb_out[(size_t)grow * 16 + t] = vv;
                else        xa_out[(size_t)grow * 2 + (t - 16)] = vv;
            }
        }
        __syncwarp();
    }
}

// ---------------------------------------------------------------------------
extern "C" void kernel_launch(void* const* d_in, const int* in_sizes, int n_in,
                              void* d_out, int out_size) {
    const float* v   = (const float*)d_in[0];
    const int*   src = (const int*)  d_in[1];
    const int*   dst = (const int*)  d_in[2];
    const float* W1  = (const float*)d_in[3];
    const float* b1  = (const float*)d_in[4];
    const float* W2  = (const float*)d_in[5];
    const float* b2  = (const float*)d_in[6];
    const float* Wa  = (const float*)d_in[7];
    const float* ba  = (const float*)d_in[8];
    const float* Wb  = (const float*)d_in[9];
    const float* bb  = (const float*)d_in[10];

    int n_nodes = in_sizes[0] / D;
    int n_edges = in_sizes[1];

    float* agg;  cudaGetSymbolAddress((void**)&agg,  g_agg);
    float* h1;   cudaGetSymbolAddress((void**)&h1,   g_h1);
    int*   deg;  cudaGetSymbolAddress((void**)&deg,  g_deg);
    int*   off;  cudaGetSymbolAddress((void**)&off,  g_off);
    int*   cur;  cudaGetSymbolAddress((void**)&cur,  g_cur);
    int*   eidx; cudaGetSymbolAddress((void**)&eidx, g_eidx);

    float* xa_out = (float*)d_out;
    float* xb_out = (float*)d_out + (size_t)n_nodes * 2;

    int edge_blocks   = (n_edges + 255) / 256;
    int scan_blocks   = (n_nodes + SCAN_B - 1) / SCAN_B;
    int gather_blocks = (n_nodes * 32 + 255) / 256;
    int wmma_blocks   = (n_nodes + 127) / 128;

    static_assert(sizeof(S2) < 96 * 1024, "smem overflow");
    cudaFuncSetAttribute(gemm2_wmma,
                         cudaFuncAttributeMaxDynamicSharedMemorySize,
                         (int)sizeof(S2));

    // ---- CSR build ----
    hist_kernel<<<edge_blocks, 256>>>(dst, deg, n_edges);
    scan_kernel<<<scan_blocks, SCAN_B>>>(deg, off, cur, n_nodes);
    fill_kernel<<<edge_blocks, 256>>>(src, dst, cur, eidx, deg,
                                      n_edges, n_nodes);

    // ---- Layer 1 ----
    gather_kernel<<<gather_blocks, 256>>>(v, eidx, off, agg, n_nodes);
    gemm1_wmma<<<wmma_blocks, 256>>>(agg, W1, b1, h1, n_nodes);

    // ---- Layer 2 + heads ----
    gather_kernel<<<gather_blocks, 256>>>(h1, eidx, off, agg, n_nodes);
    gemm2_wmma<<<wmma_blocks, 256, sizeof(S2)>>>(agg, W2, b2, Wa, ba, Wb, bb,
                                                 xa_out, xb_out, n_nodes);
}

// round 14
// speedup vs baseline: 1.7569x; 1.0038x over previous
#include <cuda_runtime.h>
#include <cuda_fp16.h>
#include <mma.h>

using namespace nvcuda;

#define N_NODES_MAX 50000
#define N_EDGES_MAX 800000
#define D 64
#define CAP 128   // bucket capacity per node; Poisson(16) => deg>128 ~impossible

// Scratch (no cudaMalloc allowed). BSS zero at load; kernels re-zero their
// counters after last use each call, so every call starts clean.
__device__ float g_h1    [N_NODES_MAX * D];
__device__ float g_agg   [N_NODES_MAX * D];
__device__ int   g_cnt   [N_NODES_MAX];          // per-node edge count
__device__ int   g_bucket[N_NODES_MAX * CAP];    // src indices per dst
__device__ int   g_ovfs  [N_EDGES_MAX];          // overflow src
__device__ int   g_ovfd  [N_EDGES_MAX];          // overflow dst
__device__ int   g_novf  [1];                    // overflow count

// ---------------------------------------------------------------------------
// Build: one pass. Claim slot in dst's bucket; spill to overflow list if full.
// ---------------------------------------------------------------------------
__global__ void build_kernel(const int* __restrict__ src,
                             const int* __restrict__ dst,
                             int* __restrict__ cnt, int* __restrict__ bucket,
                             int* __restrict__ ovfs, int* __restrict__ ovfd,
                             int* __restrict__ novf, int n_edges) {
    int i = blockIdx.x * blockDim.x + threadIdx.x;
    if (i >= n_edges) return;
    int d = __ldg(dst + i);
    int s = __ldg(src + i);
    int p = atomicAdd(cnt + d, 1);
    if (p < CAP) {
        bucket[(size_t)d * CAP + p] = s;
    } else {
        int q = atomicAdd(novf, 1);
        ovfs[q] = s;
        ovfd[q] = d;
    }
}

// ---------------------------------------------------------------------------
// Gather: warp per node; half-warp per edge (16 x float4), predicated 4-deep.
// Reads deg from cnt; bucket row is contiguous. Over-capacity nodes scan the
// overflow list themselves (never taken for sane inputs, correct for all).
// clear=1 on the last gather zeroes cnt for the next call.
// ---------------------------------------------------------------------------
__global__ __launch_bounds__(256) void gather_kernel(
    const float* __restrict__ h, const int* __restrict__ bucket,
    int* __restrict__ cnt,
    const int* __restrict__ ovfs, const int* __restrict__ ovfd,
    const int* __restrict__ novf,
    float* __restrict__ agg, int n, int clear) {
    int warp = (blockIdx.x * blockDim.x + threadIdx.x) >> 5;
    if (warp >= n) return;
    int lane = threadIdx.x & 31;
    int half = lane >> 4;
    int hl   = lane & 15;
    int deg  = __ldg(cnt + warp);
    int eb   = min(deg, CAP);
    int o    = warp * CAP;
    int e    = o + eb;
    int last = max(o, e - 1);

    float4 acc = make_float4(0.f, 0.f, 0.f, 0.f);
    for (int i = o + half; i < e; i += 8) {
        int j1 = i + 2, j2 = i + 4, j3 = i + 6;
        int s0 = __ldg(bucket + i);
        int s1 = __ldg(bucket + min(j1, last));
        int s2 = __ldg(bucket + min(j2, last));
        int s3 = __ldg(bucket + min(j3, last));
        float m1 = (j1 < e) ? 1.f : 0.f;
        float m2 = (j2 < e) ? 1.f : 0.f;
        float m3 = (j3 < e) ? 1.f : 0.f;
        float4 v0 = *reinterpret_cast<const float4*>(h + (size_t)s0 * D + hl * 4);
        float4 v1 = *reinterpret_cast<const float4*>(h + (size_t)s1 * D + hl * 4);
        float4 v2 = *reinterpret_cast<const float4*>(h + (size_t)s2 * D + hl * 4);
        float4 v3 = *reinterpret_cast<const float4*>(h + (size_t)s3 * D + hl * 4);
        acc.x += v0.x + m1 * v1.x + m2 * v2.x + m3 * v3.x;
        acc.y += v0.y + m1 * v1.y + m2 * v2.y + m3 * v3.y;
        acc.z += v0.z + m1 * v1.z + m2 * v2.z + m3 * v3.z;
        acc.w += v0.w + m1 * v1.w + m2 * v2.w + m3 * v3.w;
    }

    if (deg > CAP) {   // correctness fallback; ~never taken
        int nov = __ldg(novf);
        for (int j = half; j < nov; j += 2) {
            if (__ldg(ovfd + j) == warp) {
                int s = __ldg(ovfs + j);
                float4 vv = *reinterpret_cast<const float4*>(
                    h + (size_t)s * D + hl * 4);
                acc.x += vv.x; acc.y += vv.y; acc.z += vv.z; acc.w += vv.w;
            }
        }
    }

    acc.x += __shfl_down_sync(0xffffffffu, acc.x, 16);
    acc.y += __shfl_down_sync(0xffffffffu, acc.y, 16);
    acc.z += __shfl_down_sync(0xffffffffu, acc.z, 16);
    acc.w += __shfl_down_sync(0xffffffffu, acc.w, 16);
    if (half == 0)
        *reinterpret_cast<float4*>(agg + (size_t)warp * D + hl * 4) = acc;
    if (clear && lane == 0) cnt[warp] = 0;
}

// ---------------------------------------------------------------------------
// Shared helper: stage a 128x64 fp32 tile into fp16 smem (zero-padded rows)
// ---------------------------------------------------------------------------
__device__ __forceinline__ void stage_tile_f16(
    const float* __restrict__ X, int base, int n, int tid,
    __half (*Xs)[72]) {
    for (int i = tid; i < 128 * 16; i += 256) {
        int r = i >> 4, c4 = i & 15;
        float4 xv = (base + r < n)
            ? *reinterpret_cast<const float4*>(X + (size_t)(base + r) * D + c4 * 4)
            : make_float4(0.f, 0.f, 0.f, 0.f);
        __half2* p = reinterpret_cast<__half2*>(&Xs[r][c4 * 4]);
        p[0] = __floats2half2_rn(xv.x, xv.y);
        p[1] = __floats2half2_rn(xv.z, xv.w);
    }
}

// ---------------------------------------------------------------------------
// Layer-1 GEMM via WMMA (R13-proven): h1 = relu(agg @ W1 + b1)
// ---------------------------------------------------------------------------
__global__ __launch_bounds__(256) void gemm1_wmma(
    const float* __restrict__ X, const float* __restrict__ W,
    const float* __restrict__ b, float* __restrict__ Y, int n) {
    __shared__ __align__(16) __half Xs[128][72];
    __shared__ __align__(16) __half Ws[64][72];
    __shared__ __align__(16) float  stage[8][16][16];
    __shared__ float bs[64];
    int tid = threadIdx.x, wid = tid >> 5, lane = tid & 31;
    int base = blockIdx.x * 128;

    for (int i = tid; i < 64 * 64; i += 256)
        Ws[i >> 6][i & 63] = __float2half(W[i]);
    if (tid < 64) bs[tid] = b[tid];
    stage_tile_f16(X, base, n, tid, Xs);
    __syncthreads();

    int r0 = wid * 16;
    for (int nt = 0; nt < 4; nt++) {
        wmma::fragment<wmma::accumulator, 16, 16, 16, float> c;
        wmma::fill_fragment(c, 0.f);
        #pragma unroll
        for (int kt = 0; kt < 4; kt++) {
            wmma::fragment<wmma::matrix_a, 16, 16, 16, half, wmma::row_major> a;
            wmma::fragment<wmma::matrix_b, 16, 16, 16, half, wmma::row_major> bf;
            wmma::load_matrix_sync(a,  &Xs[r0][kt * 16], 72);
            wmma::load_matrix_sync(bf, &Ws[kt * 16][nt * 16], 72);
            wmma::mma_sync(c, a, bf, c);
        }
        wmma::store_matrix_sync(&stage[wid][0][0], c, 16, wmma::mem_row_major);
        __syncwarp();
        for (int i = lane; i < 256; i += 32) {
            int rr = i >> 4, cc = i & 15;
            int grow = base + r0 + rr;
            if (grow < n) {
                float vv = stage[wid][rr][cc] + bs[nt * 16 + cc];
                Y[(size_t)grow * D + nt * 16 + cc] = fmaxf(vv, 0.f);
            }
        }
        __syncwarp();
    }
}

// ---------------------------------------------------------------------------
// Layer-2 GEMM + heads via WMMA (R13-proven, + novf reset at tail)
// ---------------------------------------------------------------------------
struct S2 {
    __half Xs[128][72];
    __half Ws[64][72];
    __half Hs[128][72];
    __half Whs[64][40];
    float  stage[8][16][16];
    float  bs[64];
    float  bh[32];
};

__global__ __launch_bounds__(256) void gemm2_wmma(
    const float* __restrict__ X, const float* __restrict__ W,
    const float* __restrict__ b,
    const float* __restrict__ Wa, const float* __restrict__ ba,
    const float* __restrict__ Wb, const float* __restrict__ bb,
    float* __restrict__ xa_out, float* __restrict__ xb_out,
    int* __restrict__ novf, int n) {
    extern __shared__ __align__(16) char smem2[];
    S2* s = reinterpret_cast<S2*>(smem2);
    int tid = threadIdx.x, wid = tid >> 5, lane = tid & 31;
    int base = blockIdx.x * 128;

    if (blockIdx.x == 0 && tid == 0) *novf = 0;   // reset for next call

    for (int i = tid; i < 64 * 64; i += 256)
        s->Ws[i >> 6][i & 63] = __float2half(W[i]);
    for (int i = tid; i < 64 * 32; i += 256) {
        int k = i >> 5, t = i & 31;
        float wv = (t < 16) ? Wb[k * 16 + t]
                 : (t < 18) ? Wa[k * 2 + (t - 16)] : 0.f;
        s->Whs[k][t] = __float2half(wv);
    }
    if (tid < 64) s->bs[tid] = b[tid];
    if (tid < 32) s->bh[tid] = (tid < 16) ? bb[tid]
                              : (tid < 18) ? ba[tid - 16] : 0.f;
    stage_tile_f16(X, base, n, tid, s->Xs);
    __syncthreads();

    int r0 = wid * 16;
    for (int nt = 0; nt < 4; nt++) {
        wmma::fragment<wmma::accumulator, 16, 16, 16, float> c;
        wmma::fill_fragment(c, 0.f);
        #pragma unroll
        for (int kt = 0; kt < 4; kt++) {
            wmma::fragment<wmma::matrix_a, 16, 16, 16, half, wmma::row_major> a;
            wmma::fragment<wmma::matrix_b, 16, 16, 16, half, wmma::row_major> bf;
            wmma::load_matrix_sync(a,  &s->Xs[r0][kt * 16], 72);
            wmma::load_matrix_sync(bf, &s->Ws[kt * 16][nt * 16], 72);
            wmma::mma_sync(c, a, bf, c);
        }
        wmma::store_matrix_sync(&s->stage[wid][0][0], c, 16, wmma::mem_row_major);
        __syncwarp();
        for (int i = lane; i < 256; i += 32) {
            int rr = i >> 4, cc = i & 15;
            float vv = fmaxf(s->stage[wid][rr][cc] + s->bs[nt * 16 + cc], 0.f);
            s->Hs[r0 + rr][nt * 16 + cc] = __float2half(vv);
        }
        __syncwarp();
    }

    for (int nt = 0; nt < 2; nt++) {
        wmma::fragment<wmma::accumulator, 16, 16, 16, float> c;
        wmma::fill_fragment(c, 0.f);
        #pragma unroll
        for (int kt = 0; kt < 4; kt++) {
            wmma::fragment<wmma::matrix_a, 16, 16, 16, half, wmma::row_major> a;
            wmma::fragment<wmma::matrix_b, 16, 16, 16, half, wmma::row_major> bf;
            wmma::load_matrix_sync(a,  &s->Hs[r0][kt * 16], 72);
            wmma::load_matrix_sync(bf, &s->Whs[kt * 16][nt * 16], 40);
            wmma::mma_sync(c, a, bf, c);
        }
        wmma::store_matrix_sync(&s->stage[wid][0][0], c, 16, wmma::mem_row_major);
        __syncwarp();
        for (int i = lane; i < 256; i += 32) {
            int rr = i >> 4, cc = i & 15;
            int t = nt * 16 + cc;
            int grow = base + r0 + rr;
            if (grow < n && t < 18) {
                float vv = s->stage[wid][rr][cc] + s->bh[t];
                if (t < 16) xb_out[(size_t)grow * 16 + t] = vv;
                else        xa_out[(size_t)grow * 2 + (t - 16)] = vv;
            }
        }
        __syncwarp();
    }
}

// ---------------------------------------------------------------------------
extern "C" void kernel_launch(void* const* d_in, const int* in_sizes, int n_in,
                              void* d_out, int out_size) {
    const float* v   = (const float*)d_in[0];
    const int*   src = (const int*)  d_in[1];
    const int*   dst = (const int*)  d_in[2];
    const float* W1  = (const float*)d_in[3];
    const float* b1  = (const float*)d_in[4];
    const float* W2  = (const float*)d_in[5];
    const float* b2  = (const float*)d_in[6];
    const float* Wa  = (const float*)d_in[7];
    const float* ba  = (const float*)d_in[8];
    const float* Wb  = (const float*)d_in[9];
    const float* bb  = (const float*)d_in[10];

    int n_nodes = in_sizes[0] / D;
    int n_edges = in_sizes[1];

    float* agg;    cudaGetSymbolAddress((void**)&agg,    g_agg);
    float* h1;     cudaGetSymbolAddress((void**)&h1,     g_h1);
    int*   cnt;    cudaGetSymbolAddress((void**)&cnt,    g_cnt);
    int*   bucket; cudaGetSymbolAddress((void**)&bucket, g_bucket);
    int*   ovfs;   cudaGetSymbolAddress((void**)&ovfs,   g_ovfs);
    int*   ovfd;   cudaGetSymbolAddress((void**)&ovfd,   g_ovfd);
    int*   novf;   cudaGetSymbolAddress((void**)&novf,   g_novf);

    float* xa_out = (float*)d_out;
    float* xb_out = (float*)d_out + (size_t)n_nodes * 2;

    int edge_blocks   = (n_edges + 255) / 256;
    int gather_blocks = (n_nodes * 32 + 255) / 256;
    int wmma_blocks   = (n_nodes + 127) / 128;

    static_assert(sizeof(S2) < 96 * 1024, "smem overflow");
    cudaFuncSetAttribute(gemm2_wmma,
                         cudaFuncAttributeMaxDynamicSharedMemorySize,
                         (int)sizeof(S2));

    // ---- build (single kernel; cnt/novf pre-zeroed by previous call) ----
    build_kernel<<<edge_blocks, 256>>>(src, dst, cnt, bucket,
                                       ovfs, ovfd, novf, n_edges);

    // ---- Layer 1 ----
    gather_kernel<<<gather_blocks, 256>>>(v, bucket, cnt, ovfs, ovfd, novf,
                                          agg, n_nodes, 0);
    gemm1_wmma<<<wmma_blocks, 256>>>(agg, W1, b1, h1, n_nodes);

    // ---- Layer 2 + heads ----
    gather_kernel<<<gather_blocks, 256>>>(h1, bucket, cnt, ovfs, ovfd, novf,
                                          agg, n_nodes, 1);
    gemm2_wmma<<<wmma_blocks, 256, sizeof(S2)>>>(agg, W2, b2, Wa, ba, Wb, bb,
                                                 xa_out, xb_out, novf, n_nodes);
}

// round 15
// speedup vs baseline: 1.8001x; 1.0246x over previous
#include <cuda_runtime.h>
#include <cuda_fp16.h>
#include <mma.h>

using namespace nvcuda;

#define N_NODES_MAX 50000
#define N_EDGES_MAX 800000
#define D 64
#define CAP 128   // bucket capacity per node; Poisson(16) => deg>128 ~impossible

// Scratch (no cudaMalloc allowed). BSS zero at load; kernels re-zero their
// counters after last use each call, so every call starts clean.
__device__ float g_h1    [N_NODES_MAX * D];
__device__ float g_agg   [N_NODES_MAX * D];
__device__ int   g_cnt   [N_NODES_MAX];          // per-node edge count
__device__ int   g_bucket[N_NODES_MAX * CAP];    // src indices per dst
__device__ int   g_ovfs  [N_EDGES_MAX];          // overflow src
__device__ int   g_ovfd  [N_EDGES_MAX];          // overflow dst
__device__ int   g_novf  [1];                    // overflow count

// ---------------------------------------------------------------------------
// Build: one pass. Claim slot in dst's bucket; spill to overflow list if full.
// ---------------------------------------------------------------------------
__global__ void build_kernel(const int* __restrict__ src,
                             const int* __restrict__ dst,
                             int* __restrict__ cnt, int* __restrict__ bucket,
                             int* __restrict__ ovfs, int* __restrict__ ovfd,
                             int* __restrict__ novf, int n_edges) {
    int i = blockIdx.x * blockDim.x + threadIdx.x;
    if (i >= n_edges) return;
    int d = __ldg(dst + i);
    int s = __ldg(src + i);
    int p = atomicAdd(cnt + d, 1);
    if (p < CAP) {
        bucket[(size_t)d * CAP + p] = s;
    } else {
        int q = atomicAdd(novf, 1);
        ovfs[q] = s;
        ovfd[q] = d;
    }
}

// ---------------------------------------------------------------------------
// Gather (lean, R12-shape): warp per node; half-warp per edge (16 x float4),
// predicated 4-deep. Bucket row contiguous at warp*CAP. No overflow logic.
// clear=1 on the last gather zeroes cnt for the next call.
// ---------------------------------------------------------------------------
__global__ __launch_bounds__(256, 8) void gather_kernel(
    const float* __restrict__ h, const int* __restrict__ bucket,
    int* __restrict__ cnt, float* __restrict__ agg, int n, int clear) {
    int warp = (blockIdx.x * blockDim.x + threadIdx.x) >> 5;
    if (warp >= n) return;
    int lane = threadIdx.x & 31;
    int half = lane >> 4;
    int hl   = lane & 15;
    int o    = warp * CAP;
    int e    = o + min(__ldg(cnt + warp), CAP);
    int last = max(o, e - 1);

    float4 acc = make_float4(0.f, 0.f, 0.f, 0.f);
    for (int i = o + half; i < e; i += 8) {
        int j1 = i + 2, j2 = i + 4, j3 = i + 6;
        int s0 = __ldg(bucket + i);
        int s1 = __ldg(bucket + min(j1, last));
        int s2 = __ldg(bucket + min(j2, last));
        int s3 = __ldg(bucket + min(j3, last));
        float m1 = (j1 < e) ? 1.f : 0.f;
        float m2 = (j2 < e) ? 1.f : 0.f;
        float m3 = (j3 < e) ? 1.f : 0.f;
        float4 v0 = *reinterpret_cast<const float4*>(h + (size_t)s0 * D + hl * 4);
        float4 v1 = *reinterpret_cast<const float4*>(h + (size_t)s1 * D + hl * 4);
        float4 v2 = *reinterpret_cast<const float4*>(h + (size_t)s2 * D + hl * 4);
        float4 v3 = *reinterpret_cast<const float4*>(h + (size_t)s3 * D + hl * 4);
        acc.x += v0.x + m1 * v1.x + m2 * v2.x + m3 * v3.x;
        acc.y += v0.y + m1 * v1.y + m2 * v2.y + m3 * v3.y;
        acc.z += v0.z + m1 * v1.z + m2 * v2.z + m3 * v3.z;
        acc.w += v0.w + m1 * v1.w + m2 * v2.w + m3 * v3.w;
    }
    acc.x += __shfl_down_sync(0xffffffffu, acc.x, 16);
    acc.y += __shfl_down_sync(0xffffffffu, acc.y, 16);
    acc.z += __shfl_down_sync(0xffffffffu, acc.z, 16);
    acc.w += __shfl_down_sync(0xffffffffu, acc.w, 16);
    if (half == 0)
        *reinterpret_cast<float4*>(agg + (size_t)warp * D + hl * 4) = acc;
    if (clear && lane == 0) cnt[warp] = 0;
}

// ---------------------------------------------------------------------------
// Overflow patch-up: rare path (novf==0 for sane inputs -> instant exit).
// One block; each thread atomically adds one overflow edge's full row.
// ---------------------------------------------------------------------------
__global__ __launch_bounds__(256) void overflow_kernel(
    const float* __restrict__ h,
    const int* __restrict__ ovfs, const int* __restrict__ ovfd,
    const int* __restrict__ novf, float* __restrict__ agg) {
    int nov = __ldg(novf);
    for (int j = threadIdx.x; j < nov; j += 256) {
        int s = ovfs[j], d = ovfd[j];
        const float4* hp = reinterpret_cast<const float4*>(h + (size_t)s * D);
        float4* ap = reinterpret_cast<float4*>(agg + (size_t)d * D);
        for (int k = 0; k < 16; k++) atomicAdd(ap + k, hp[k]);
    }
}

// ---------------------------------------------------------------------------
// Shared helper: stage a 128x64 fp32 tile into fp16 smem (zero-padded rows)
// ---------------------------------------------------------------------------
__device__ __forceinline__ void stage_tile_f16(
    const float* __restrict__ X, int base, int n, int tid,
    __half (*Xs)[72]) {
    for (int i = tid; i < 128 * 16; i += 256) {
        int r = i >> 4, c4 = i & 15;
        float4 xv = (base + r < n)
            ? *reinterpret_cast<const float4*>(X + (size_t)(base + r) * D + c4 * 4)
            : make_float4(0.f, 0.f, 0.f, 0.f);
        __half2* p = reinterpret_cast<__half2*>(&Xs[r][c4 * 4]);
        p[0] = __floats2half2_rn(xv.x, xv.y);
        p[1] = __floats2half2_rn(xv.z, xv.w);
    }
}

// ---------------------------------------------------------------------------
// Layer-1 GEMM via WMMA (R13-proven): h1 = relu(agg @ W1 + b1)
// ---------------------------------------------------------------------------
__global__ __launch_bounds__(256) void gemm1_wmma(
    const float* __restrict__ X, const float* __restrict__ W,
    const float* __restrict__ b, float* __restrict__ Y, int n) {
    __shared__ __align__(16) __half Xs[128][72];
    __shared__ __align__(16) __half Ws[64][72];
    __shared__ __align__(16) float  stage[8][16][16];
    __shared__ float bs[64];
    int tid = threadIdx.x, wid = tid >> 5, lane = tid & 31;
    int base = blockIdx.x * 128;

    for (int i = tid; i < 64 * 64; i += 256)
        Ws[i >> 6][i & 63] = __float2half(W[i]);
    if (tid < 64) bs[tid] = b[tid];
    stage_tile_f16(X, base, n, tid, Xs);
    __syncthreads();

    int r0 = wid * 16;
    for (int nt = 0; nt < 4; nt++) {
        wmma::fragment<wmma::accumulator, 16, 16, 16, float> c;
        wmma::fill_fragment(c, 0.f);
        #pragma unroll
        for (int kt = 0; kt < 4; kt++) {
            wmma::fragment<wmma::matrix_a, 16, 16, 16, half, wmma::row_major> a;
            wmma::fragment<wmma::matrix_b, 16, 16, 16, half, wmma::row_major> bf;
            wmma::load_matrix_sync(a,  &Xs[r0][kt * 16], 72);
            wmma::load_matrix_sync(bf, &Ws[kt * 16][nt * 16], 72);
            wmma::mma_sync(c, a, bf, c);
        }
        wmma::store_matrix_sync(&stage[wid][0][0], c, 16, wmma::mem_row_major);
        __syncwarp();
        for (int i = lane; i < 256; i += 32) {
            int rr = i >> 4, cc = i & 15;
            int grow = base + r0 + rr;
            if (grow < n) {
                float vv = stage[wid][rr][cc] + bs[nt * 16 + cc];
                Y[(size_t)grow * D + nt * 16 + cc] = fmaxf(vv, 0.f);
            }
        }
        __syncwarp();
    }
}

// ---------------------------------------------------------------------------
// Layer-2 GEMM + heads via WMMA (R13-proven, + novf reset at tail)
// ---------------------------------------------------------------------------
struct S2 {
    __half Xs[128][72];
    __half Ws[64][72];
    __half Hs[128][72];
    __half Whs[64][40];
    float  stage[8][16][16];
    float  bs[64];
    float  bh[32];
};

__global__ __launch_bounds__(256) void gemm2_wmma(
    const float* __restrict__ X, const float* __restrict__ W,
    const float* __restrict__ b,
    const float* __restrict__ Wa, const float* __restrict__ ba,
    const float* __restrict__ Wb, const float* __restrict__ bb,
    float* __restrict__ xa_out, float* __restrict__ xb_out,
    int* __restrict__ novf, int n) {
    extern __shared__ __align__(16) char smem2[];
    S2* s = reinterpret_cast<S2*>(smem2);
    int tid = threadIdx.x, wid = tid >> 5, lane = tid & 31;
    int base = blockIdx.x * 128;

    if (blockIdx.x == 0 && tid == 0) *novf = 0;   // reset for next call

    for (int i = tid; i < 64 * 64; i += 256)
        s->Ws[i >> 6][i & 63] = __float2half(W[i]);
    for (int i = tid; i < 64 * 32; i += 256) {
        int k = i >> 5, t = i & 31;
        float wv = (t < 16) ? Wb[k * 16 + t]
                 : (t < 18) ? Wa[k * 2 + (t - 16)] : 0.f;
        s->Whs[k][t] = __float2half(wv);
    }
    if (tid < 64) s->bs[tid] = b[tid];
    if (tid < 32) s->bh[tid] = (tid < 16) ? bb[tid]
                              : (tid < 18) ? ba[tid - 16] : 0.f;
    stage_tile_f16(X, base, n, tid, s->Xs);
    __syncthreads();

    int r0 = wid * 16;
    for (int nt = 0; nt < 4; nt++) {
        wmma::fragment<wmma::accumulator, 16, 16, 16, float> c;
        wmma::fill_fragment(c, 0.f);
        #pragma unroll
        for (int kt = 0; kt < 4; kt++) {
            wmma::fragment<wmma::matrix_a, 16, 16, 16, half, wmma::row_major> a;
            wmma::fragment<wmma::matrix_b, 16, 16, 16, half, wmma::row_major> bf;
            wmma::load_matrix_sync(a,  &s->Xs[r0][kt * 16], 72);
            wmma::load_matrix_sync(bf, &s->Ws[kt * 16][nt * 16], 72);
            wmma::mma_sync(c, a, bf, c);
        }
        wmma::store_matrix_sync(&s->stage[wid][0][0], c, 16, wmma::mem_row_major);
        __syncwarp();
        for (int i = lane; i < 256; i += 32) {
            int rr = i >> 4, cc = i & 15;
            float vv = fmaxf(s->stage[wid][rr][cc] + s->bs[nt * 16 + cc], 0.f);
            s->Hs[r0 + rr][nt * 16 + cc] = __float2half(vv);
        }
        __syncwarp();
    }

    for (int nt = 0; nt < 2; nt++) {
        wmma::fragment<wmma::accumulator, 16, 16, 16, float> c;
        wmma::fill_fragment(c, 0.f);
        #pragma unroll
        for (int kt = 0; kt < 4; kt++) {
            wmma::fragment<wmma::matrix_a, 16, 16, 16, half, wmma::row_major> a;
            wmma::fragment<wmma::matrix_b, 16, 16, 16, half, wmma::row_major> bf;
            wmma::load_matrix_sync(a,  &s->Hs[r0][kt * 16], 72);
            wmma::load_matrix_sync(bf, &s->Whs[kt * 16][nt * 16], 40);
            wmma::mma_sync(c, a, bf, c);
        }
        wmma::store_matrix_sync(&s->stage[wid][0][0], c, 16, wmma::mem_row_major);
        __syncwarp();
        for (int i = lane; i < 256; i += 32) {
            int rr = i >> 4, cc = i & 15;
            int t = nt * 16 + cc;
            int grow = base + r0 + rr;
            if (grow < n && t < 18) {
                float vv = s->stage[wid][rr][cc] + s->bh[t];
                if (t < 16) xb_out[(size_t)grow * 16 + t] = vv;
                else        xa_out[(size_t)grow * 2 + (t - 16)] = vv;
            }
        }
        __syncwarp();
    }
}

// ---------------------------------------------------------------------------
extern "C" void kernel_launch(void* const* d_in, const int* in_sizes, int n_in,
                              void* d_out, int out_size) {
    const float* v   = (const float*)d_in[0];
    const int*   src = (const int*)  d_in[1];
    const int*   dst = (const int*)  d_in[2];
    const float* W1  = (const float*)d_in[3];
    const float* b1  = (const float*)d_in[4];
    const float* W2  = (const float*)d_in[5];
    const float* b2  = (const float*)d_in[6];
    const float* Wa  = (const float*)d_in[7];
    const float* ba  = (const float*)d_in[8];
    const float* Wb  = (const float*)d_in[9];
    const float* bb  = (const float*)d_in[10];

    int n_nodes = in_sizes[0] / D;
    int n_edges = in_sizes[1];

    float* agg;    cudaGetSymbolAddress((void**)&agg,    g_agg);
    float* h1;     cudaGetSymbolAddress((void**)&h1,     g_h1);
    int*   cnt;    cudaGetSymbolAddress((void**)&cnt,    g_cnt);
    int*   bucket; cudaGetSymbolAddress((void**)&bucket, g_bucket);
    int*   ovfs;   cudaGetSymbolAddress((void**)&ovfs,   g_ovfs);
    int*   ovfd;   cudaGetSymbolAddress((void**)&ovfd,   g_ovfd);
    int*   novf;   cudaGetSymbolAddress((void**)&novf,   g_novf);

    float* xa_out = (float*)d_out;
    float* xb_out = (float*)d_out + (size_t)n_nodes * 2;

    int edge_blocks   = (n_edges + 255) / 256;
    int gather_blocks = (n_nodes * 32 + 255) / 256;
    int wmma_blocks   = (n_nodes + 127) / 128;

    static_assert(sizeof(S2) < 96 * 1024, "smem overflow");
    cudaFuncSetAttribute(gemm2_wmma,
                         cudaFuncAttributeMaxDynamicSharedMemorySize,
                         (int)sizeof(S2));

    // ---- build (single kernel; cnt/novf pre-zeroed by previous call) ----
    build_kernel<<<edge_blocks, 256>>>(src, dst, cnt, bucket,
                                       ovfs, ovfd, novf, n_edges);

    // ---- Layer 1 ----
    gather_kernel<<<gather_blocks, 256>>>(v, bucket, cnt, agg, n_nodes, 0);
    overflow_kernel<<<1, 256>>>(v, ovfs, ovfd, novf, agg);
    gemm1_wmma<<<wmma_blocks, 256>>>(agg, W1, b1, h1, n_nodes);

    // ---- Layer 2 + heads ----
    gather_kernel<<<gather_blocks, 256>>>(h1, bucket, cnt, agg, n_nodes, 1);
    overflow_kernel<<<1, 256>>>(h1, ovfs, ovfd, novf, agg);
    gemm2_wmma<<<wmma_blocks, 256, sizeof(S2)>>>(agg, W2, b2, Wa, ba, Wb, bb,
                                                 xa_out, xb_out, novf, n_nodes);
}